// round 14
// baseline (speedup 1.0000x reference)
#include <cuda_runtime.h>
#include <cstdint>

#define DDEPTH 8
#define HDIM   4096
#define NT     512
#define NWARP  (NT / 32)    // 16
#define HPT    8            // hidden dims per thread (512*8 = 4096)
#define EPSV   1e-6f
#define STAGES 3            // cp.async ring: 2 pairs always in flight

#define DOT4(a,b) ((a).x*(b).x + (a).y*(b).y + (a).z*(b).z + (a).w*(b).w)

__device__ __forceinline__ uint32_t smem_u32(const void* p) {
    uint32_t a;
    asm("{ .reg .u64 t; cvta.to.shared.u64 t, %1; cvt.u32.u64 %0, t; }"
        : "=r"(a) : "l"(p));
    return a;
}

__device__ __forceinline__ void cp16(uint32_t saddr, const float* g) {
    asm volatile("cp.async.cg.shared.global [%0], [%1], 16;"
                 :: "r"(saddr), "l"(g) : "memory");
}

// Persistent CTAs (2/SM), online softmax over depth PAIRS. Values flow
// gmem -> smem ring (cp.async, zero register cost in flight) -> registers.
// Depth-2 pair prefetch keeps 64 KiB/CTA outstanding through every tail.
__global__ __launch_bounds__(NT, 2)
void fullattnres_kernel(const float* __restrict__ values,
                        const float* __restrict__ query,
                        const float* __restrict__ weight,
                        float* __restrict__ out,
                        int SB)
{
    extern __shared__ float4 sbuf[];   // [STAGES][4 chunks][NT] float4
    __shared__ float4 red[2][NWARP];   // {ss0,ss1,dp0,dp1} per warp, parity buf

    const int tid  = threadIdx.x;
    const int lane = tid & 31;
    const int warp = tid >> 5;
    const int h    = tid * HPT;
    const int grid = gridDim.x;
    const size_t dstr = (size_t)SB * HDIM;

    if ((int)blockIdx.x >= SB) return;
    const int nsites = (SB - 1 - (int)blockIdx.x) / grid + 1;
    const int npairs = nsites * 4;

    // fused q*w, loaded ONCE per CTA (persistent)
    const float4 q0 = *(const float4*)(query + h);
    const float4 q1 = *(const float4*)(query + h + 4);
    const float4 w0 = *(const float4*)(weight + h);
    const float4 w1 = *(const float4*)(weight + h + 4);
    const float4 qw0 = make_float4(q0.x*w0.x, q0.y*w0.y, q0.z*w0.z, q0.w*w0.w);
    const float4 qw1 = make_float4(q1.x*w1.x, q1.y*w1.y, q1.z*w1.z, q1.w*w1.w);

    const uint32_t sb0 = smem_u32(sbuf) + (uint32_t)tid * 16u;

    // prefetch pair g into stage st (address clamped to last valid pair;
    // clamped duplicates land in stages that are never consumed)
    auto issue_pair = [&](int g, int st) {
        int gp = g;
        if (gp > npairs - 1) gp = npairs - 1;
        const int psite = (int)blockIdx.x + (gp >> 2) * grid;
        const int ppr   = gp & 3;
        const float* gb = values + (size_t)psite * HDIM + h + (size_t)(2 * ppr) * dstr;
        const uint32_t sa = sb0 + (uint32_t)(st * 4 * NT) * 16u;
        cp16(sa,                 gb);
        cp16(sa + NT * 16u,      gb + 4);
        cp16(sa + 2u * NT * 16u, gb + dstr);
        cp16(sa + 3u * NT * 16u, gb + dstr + 4);
        asm volatile("cp.async.commit_group;" ::: "memory");
    };

    // prologue: pairs 0 and 1 in flight
    issue_pair(0, 0);
    issue_pair(1, 1);

    int parity = 0;
    int stage  = 0;   // stage of the pair being consumed (g % STAGES)
    int pstage = 2;   // stage for the pair being prefetched ((g+2) % STAGES)

    for (int si = 0; si < nsites; si++) {
        const int site = (int)blockIdx.x + si * grid;

        float  m = -3.402823466e38f;
        float  s = 0.f;
        float4 acc0 = make_float4(0.f, 0.f, 0.f, 0.f);
        float4 acc1 = make_float4(0.f, 0.f, 0.f, 0.f);

        #pragma unroll
        for (int pr = 0; pr < 4; pr++) {
            const int g = si * 4 + pr;

            // keep the pipe full: issue pair g+2, then wait for pair g
            issue_pair(g + 2, pstage);
            asm volatile("cp.async.wait_group 2;" ::: "memory");

            // consume pair g from its stage: 4 conflict-free LDS.128
            const float4* cb = sbuf + stage * 4 * NT + tid;
            const float4 a0 = cb[0];
            const float4 a1 = cb[NT];
            const float4 b0 = cb[2 * NT];
            const float4 b1 = cb[3 * NT];

            // partials for depths 2pr (a) and 2pr+1 (b)
            float ss0 = DOT4(a0, a0) + DOT4(a1, a1);
            float dp0 = DOT4(qw0, a0) + DOT4(qw1, a1);
            float ss1 = DOT4(b0, b0) + DOT4(b1, b1);
            float dp1 = DOT4(qw0, b0) + DOT4(qw1, b1);

            // warp butterfly over the 4 scalars
            #pragma unroll
            for (int off = 16; off > 0; off >>= 1) {
                ss0 += __shfl_xor_sync(0xFFFFFFFFu, ss0, off);
                ss1 += __shfl_xor_sync(0xFFFFFFFFu, ss1, off);
                dp0 += __shfl_xor_sync(0xFFFFFFFFu, dp0, off);
                dp1 += __shfl_xor_sync(0xFFFFFFFFu, dp1, off);
            }
            if (lane == 0)
                red[parity][warp] = make_float4(ss0, ss1, dp0, dp1);
            __syncthreads();

            // distributed cross-warp scan: 1 LDS.128 + 4-round f4 butterfly
            float4 t = red[parity][lane & 15];
            #pragma unroll
            for (int off = 8; off > 0; off >>= 1) {
                t.x += __shfl_xor_sync(0xFFFFFFFFu, t.x, off);
                t.y += __shfl_xor_sync(0xFFFFFFFFu, t.y, off);
                t.z += __shfl_xor_sync(0xFFFFFFFFu, t.z, off);
                t.w += __shfl_xor_sync(0xFFFFFFFFu, t.w, off);
            }
            parity ^= 1;

            const float l0 = t.z * rsqrtf(t.x * (1.0f / HDIM) + EPSV);
            const float l1 = t.w * rsqrtf(t.y * (1.0f / HDIM) + EPSV);

            // joint online-softmax update for both depths
            const float mn = fmaxf(m, fmaxf(l0, l1));
            const float cs = __expf(m - mn);     // first pair: exp(-inf)=0
            const float e0 = __expf(l0 - mn);
            const float e1 = __expf(l1 - mn);
            s = s * cs + e0 + e1;
            acc0.x = acc0.x * cs + e0 * a0.x + e1 * b0.x;
            acc0.y = acc0.y * cs + e0 * a0.y + e1 * b0.y;
            acc0.z = acc0.z * cs + e0 * a0.z + e1 * b0.z;
            acc0.w = acc0.w * cs + e0 * a0.w + e1 * b0.w;
            acc1.x = acc1.x * cs + e0 * a1.x + e1 * b1.x;
            acc1.y = acc1.y * cs + e0 * a1.y + e1 * b1.y;
            acc1.z = acc1.z * cs + e0 * a1.z + e1 * b1.z;
            acc1.w = acc1.w * cs + e0 * a1.w + e1 * b1.w;
            m = mn;

            // advance ring cursors
            if (++stage  == STAGES) stage  = 0;
            if (++pstage == STAGES) pstage = 0;
        }

        // finalize + store this site
        const float inv = 1.0f / s;
        const size_t ob = (size_t)site * HDIM + h;
        *(float4*)(out + ob)     = make_float4(acc0.x*inv, acc0.y*inv, acc0.z*inv, acc0.w*inv);
        *(float4*)(out + ob + 4) = make_float4(acc1.x*inv, acc1.y*inv, acc1.z*inv, acc1.w*inv);
    }

    // drain remaining cp.async groups before exit
    asm volatile("cp.async.wait_group 0;" ::: "memory");
}

extern "C" void kernel_launch(void* const* d_in, const int* in_sizes, int n_in,
                              void* d_out, int out_size)
{
    const float* values = (const float*)d_in[0];  // [D,S,B,H]
    const float* query  = (const float*)d_in[1];  // [H]
    const float* weight = (const float*)d_in[2];  // [H]
    float* out = (float*)d_out;                   // [S,B,H]

    const int H  = in_sizes[1];                   // 4096
    const int SB = out_size / H;                  // S*B = 4096

    const size_t smem_bytes = (size_t)STAGES * 4 * NT * sizeof(float4); // 96 KiB
    cudaFuncSetAttribute(fullattnres_kernel,
                         cudaFuncAttributeMaxDynamicSharedMemorySize,
                         (int)smem_bytes);

    int sms = 148;
    cudaDeviceGetAttribute(&sms, cudaDevAttrMultiProcessorCount, 0);
    int grid = 2 * sms;                           // persistent: 2 CTAs per SM
    if (grid > SB) grid = SB;

    fullattnres_kernel<<<grid, NT, smem_bytes>>>(values, query, weight, out, SB);
}

// round 15
// speedup vs baseline: 1.6183x; 1.6183x over previous
#include <cuda_runtime.h>
#include <cstdint>

#define DDEPTH 8
#define HDIM   4096
#define NT     512
#define NWARP  (NT / 32)    // 16
#define HPT    8            // hidden dims per thread (512*8 = 4096)
#define EPSV   1e-6f
#define STAGES 3            // TMA ring: 2 pairs always in flight
#define ROW_BYTES  (HDIM * 4)        // one depth row of one site: 16 KiB
#define PAIR_BYTES (2 * ROW_BYTES)   // 32 KiB

#define DOT4(a,b) ((a).x*(b).x + (a).y*(b).y + (a).z*(b).z + (a).w*(b).w)

__device__ __forceinline__ uint32_t smem_u32(const void* p) {
    uint32_t a;
    asm("{ .reg .u64 t; cvta.to.shared.u64 t, %1; cvt.u32.u64 %0, t; }"
        : "=r"(a) : "l"(p));
    return a;
}

__device__ __forceinline__ void mbar_init(uint32_t mb, uint32_t cnt) {
    asm volatile("mbarrier.init.shared.b64 [%0], %1;" :: "r"(mb), "r"(cnt) : "memory");
}
__device__ __forceinline__ void mbar_expect_tx(uint32_t mb, uint32_t bytes) {
    asm volatile("mbarrier.arrive.expect_tx.shared.b64 _, [%0], %1;"
                 :: "r"(mb), "r"(bytes) : "memory");
}
__device__ __forceinline__ void mbar_arrive(uint32_t mb) {
    asm volatile("mbarrier.arrive.shared.b64 _, [%0];" :: "r"(mb) : "memory");
}
__device__ __forceinline__ void mbar_wait(uint32_t mb, uint32_t parity) {
    uint32_t done;
    asm volatile(
        "{ .reg .pred p;"
        "  mbarrier.try_wait.parity.acquire.cta.shared::cta.b64 p, [%1], %2;"
        "  selp.b32 %0, 1, 0, p; }"
        : "=r"(done) : "r"(mb), "r"(parity) : "memory");
    if (!done) {
        asm volatile(
            "{ .reg .pred P1;"
            "WAIT_LOOP_%=:"
            "  mbarrier.try_wait.parity.acquire.cta.shared::cta.b64 P1, [%0], %1, 0x989680;"
            "  @P1 bra.uni WAIT_DONE_%=;"
            "  bra.uni WAIT_LOOP_%=;"
            "WAIT_DONE_%=: }"
            :: "r"(mb), "r"(parity) : "memory");
    }
}
// engine-driven bulk copy gmem->smem; completion via mbarrier complete_tx
__device__ __forceinline__ void bulk_cp(uint32_t sdst, const float* gsrc,
                                        uint32_t bytes, uint32_t mb) {
    asm volatile(
        "cp.async.bulk.shared::cluster.global.mbarrier::complete_tx::bytes "
        "[%0], [%1], %2, [%3];"
        :: "r"(sdst), "l"(gsrc), "r"(bytes), "r"(mb) : "memory");
}

// Persistent CTAs (2/SM), online softmax over depth PAIRS. Values flow
// gmem -> smem ring via cp.async.bulk (one issuing thread, zero LSU/register
// cost in flight) -> registers. 64 KiB/CTA outstanding through every tail.
__global__ __launch_bounds__(NT, 2)
void fullattnres_kernel(const float* __restrict__ values,
                        const float* __restrict__ query,
                        const float* __restrict__ weight,
                        float* __restrict__ out,
                        int SB)
{
    extern __shared__ float sbuf[];    // [STAGES][2][HDIM] floats (96 KiB)
    __shared__ float4 red[2][NWARP];   // {ss0,ss1,dp0,dp1} per warp, parity buf
    __shared__ unsigned long long full_b[STAGES], empty_b[STAGES];

    const int tid  = threadIdx.x;
    const int lane = tid & 31;
    const int warp = tid >> 5;
    const int h    = tid * HPT;
    const int grid = gridDim.x;
    const size_t dstr = (size_t)SB * HDIM;

    if ((int)blockIdx.x >= SB) return;
    const int nsites = (SB - 1 - (int)blockIdx.x) / grid + 1;
    const int npairs = nsites * 4;

    uint32_t full_a[STAGES], empty_a[STAGES];
    #pragma unroll
    for (int i = 0; i < STAGES; i++) {
        full_a[i]  = smem_u32(&full_b[i]);
        empty_a[i] = smem_u32(&empty_b[i]);
    }
    if (tid == 0) {
        #pragma unroll
        for (int i = 0; i < STAGES; i++) { mbar_init(full_a[i], 1); mbar_init(empty_a[i], 1); }
    }
    __syncthreads();

    // fused q*w, loaded ONCE per CTA (persistent)
    const float4 q0 = *(const float4*)(query + h);
    const float4 q1 = *(const float4*)(query + h + 4);
    const float4 w0 = *(const float4*)(weight + h);
    const float4 w1 = *(const float4*)(weight + h + 4);
    const float4 qw0 = make_float4(q0.x*w0.x, q0.y*w0.y, q0.z*w0.z, q0.w*w0.w);
    const float4 qw1 = make_float4(q1.x*w1.x, q1.y*w1.y, q1.z*w1.z, q1.w*w1.w);

    const uint32_t sbase = smem_u32(sbuf);

    // producer cursor (tid 0 only issues); phase=1 so first empty-wait passes
    int p_stage = 0, p_phase = 1;
    // consumer cursor
    int c_stage = 0, c_phase = 0;

    auto issue_pair = [&](int g) {   // tid==0 only
        mbar_wait(empty_a[p_stage], (uint32_t)p_phase);
        const int psite = (int)blockIdx.x + (g >> 2) * grid;
        const int ppr   = g & 3;
        const float* gb = values + (size_t)psite * HDIM + (size_t)(2 * ppr) * dstr;
        const uint32_t sd = sbase + (uint32_t)p_stage * PAIR_BYTES;
        mbar_expect_tx(full_a[p_stage], PAIR_BYTES);
        bulk_cp(sd,             gb,        ROW_BYTES, full_a[p_stage]);
        bulk_cp(sd + ROW_BYTES, gb + dstr, ROW_BYTES, full_a[p_stage]);
        if (++p_stage == STAGES) { p_stage = 0; p_phase ^= 1; }
    };

    // prologue: pairs 0 and 1 in flight
    if (tid == 0) { issue_pair(0); issue_pair(1); }

    int parity = 0;

    for (int si = 0; si < nsites; si++) {
        const int site = (int)blockIdx.x + si * grid;

        float  m = -3.402823466e38f;
        float  s = 0.f;
        float4 acc0 = make_float4(0.f, 0.f, 0.f, 0.f);
        float4 acc1 = make_float4(0.f, 0.f, 0.f, 0.f);

        #pragma unroll
        for (int pr = 0; pr < 4; pr++) {
            const int g = si * 4 + pr;

            // keep the pipe 2 pairs deep (engine does the copy; SM moves on)
            if (tid == 0 && g + 2 < npairs) issue_pair(g + 2);

            // wait for pair g, then 4 conflict-free LDS.128
            mbar_wait(full_a[c_stage], (uint32_t)c_phase);
            const float* cb = sbuf + c_stage * 2 * HDIM + h;
            const float4 a0 = *(const float4*)(cb);
            const float4 a1 = *(const float4*)(cb + 4);
            const float4 b0 = *(const float4*)(cb + HDIM);
            const float4 b1 = *(const float4*)(cb + HDIM + 4);

            // partials for depths 2pr (a) and 2pr+1 (b)
            float ss0 = DOT4(a0, a0) + DOT4(a1, a1);
            float dp0 = DOT4(qw0, a0) + DOT4(qw1, a1);
            float ss1 = DOT4(b0, b0) + DOT4(b1, b1);
            float dp1 = DOT4(qw0, b0) + DOT4(qw1, b1);

            // warp butterfly over the 4 scalars
            #pragma unroll
            for (int off = 16; off > 0; off >>= 1) {
                ss0 += __shfl_xor_sync(0xFFFFFFFFu, ss0, off);
                ss1 += __shfl_xor_sync(0xFFFFFFFFu, ss1, off);
                dp0 += __shfl_xor_sync(0xFFFFFFFFu, dp0, off);
                dp1 += __shfl_xor_sync(0xFFFFFFFFu, dp1, off);
            }
            if (lane == 0)
                red[parity][warp] = make_float4(ss0, ss1, dp0, dp1);
            __syncthreads();   // also proves: every thread's LDS reads are done

            // stage g is now fully consumed -> free it for the producer
            if (tid == 0) mbar_arrive(empty_a[c_stage]);
            if (++c_stage == STAGES) { c_stage = 0; c_phase ^= 1; }

            // distributed cross-warp scan: 1 LDS.128 + 4-round f4 butterfly
            float4 t = red[parity][lane & 15];
            #pragma unroll
            for (int off = 8; off > 0; off >>= 1) {
                t.x += __shfl_xor_sync(0xFFFFFFFFu, t.x, off);
                t.y += __shfl_xor_sync(0xFFFFFFFFu, t.y, off);
                t.z += __shfl_xor_sync(0xFFFFFFFFu, t.z, off);
                t.w += __shfl_xor_sync(0xFFFFFFFFu, t.w, off);
            }
            parity ^= 1;

            const float l0 = t.z * rsqrtf(t.x * (1.0f / HDIM) + EPSV);
            const float l1 = t.w * rsqrtf(t.y * (1.0f / HDIM) + EPSV);

            // joint online-softmax update for both depths
            const float mn = fmaxf(m, fmaxf(l0, l1));
            const float cs = __expf(m - mn);     // first pair: exp(-inf)=0
            const float e0 = __expf(l0 - mn);
            const float e1 = __expf(l1 - mn);
            s = s * cs + e0 + e1;
            acc0.x = acc0.x * cs + e0 * a0.x + e1 * b0.x;
            acc0.y = acc0.y * cs + e0 * a0.y + e1 * b0.y;
            acc0.z = acc0.z * cs + e0 * a0.z + e1 * b0.z;
            acc0.w = acc0.w * cs + e0 * a0.w + e1 * b0.w;
            acc1.x = acc1.x * cs + e0 * a1.x + e1 * b1.x;
            acc1.y = acc1.y * cs + e0 * a1.y + e1 * b1.y;
            acc1.z = acc1.z * cs + e0 * a1.z + e1 * b1.z;
            acc1.w = acc1.w * cs + e0 * a1.w + e1 * b1.w;
            m = mn;
        }

        // finalize + store this site
        const float inv = 1.0f / s;
        const size_t ob = (size_t)site * HDIM + h;
        *(float4*)(out + ob)     = make_float4(acc0.x*inv, acc0.y*inv, acc0.z*inv, acc0.w*inv);
        *(float4*)(out + ob + 4) = make_float4(acc1.x*inv, acc1.y*inv, acc1.z*inv, acc1.w*inv);
    }
}

extern "C" void kernel_launch(void* const* d_in, const int* in_sizes, int n_in,
                              void* d_out, int out_size)
{
    const float* values = (const float*)d_in[0];  // [D,S,B,H]
    const float* query  = (const float*)d_in[1];  // [H]
    const float* weight = (const float*)d_in[2];  // [H]
    float* out = (float*)d_out;                   // [S,B,H]

    const int H  = in_sizes[1];                   // 4096
    const int SB = out_size / H;                  // S*B = 4096

    const size_t smem_bytes = (size_t)STAGES * PAIR_BYTES;  // 96 KiB
    cudaFuncSetAttribute(fullattnres_kernel,
                         cudaFuncAttributeMaxDynamicSharedMemorySize,
                         (int)smem_bytes);

    int sms = 148;
    cudaDeviceGetAttribute(&sms, cudaDevAttrMultiProcessorCount, 0);
    int grid = 2 * sms;                           // persistent: 2 CTAs per SM
    if (grid > SB) grid = SB;

    fullattnres_kernel<<<grid, NT, smem_bytes>>>(values, query, weight, out, SB);
}